// round 7
// baseline (speedup 1.0000x reference)
#include <cuda_runtime.h>
#include <cuda_fp16.h>
#include <math.h>

#define D 64
#define V_MAX 100000
#define NBMAX 128
#define E_NG_MAX  2000000
#define E_LOC_MAX 1000000
#define E_INT_MAX 1200000
#define E_SIM_MAX  800000

// ---------------- scratch ------------------------------------------------------
__device__ float   g_wL[V_MAX];
__device__ float   g_wG[V_MAX];
__device__ __half2 g_WNL[V_MAX * 32];
__device__ __half2 g_WNG[V_MAX * 32];

__device__ int g_cnt[4 * V_MAX];
__device__ int g_off[4 * (V_MAX + 1)];
__device__ int g_cur[4 * V_MAX];
__device__ int g_bsum[4 * NBMAX];
__device__ int g_binNG[E_NG_MAX];
__device__ int g_binLOC[E_LOC_MAX];
__device__ int g_binI[E_INT_MAX];
__device__ int g_binS[E_SIM_MAX];

__device__ __forceinline__ float tanh_fast(float x) {
    float r;
    asm("tanh.approx.f32 %0, %1;" : "=f"(r) : "f"(x));
    return r;
}

// ---------------- scores helper (interleaved float2 layout, 4 nodes/warp) ----------
__device__ __forceinline__ void score4(
    const float2* __restrict__ N2, const float* __restrict__ sW,
    const float2* __restrict__ sw2, float* __restrict__ wOut,
    __half2* __restrict__ WN, int base, int V, int lane)
{
    float2 n[4];
    #pragma unroll
    for (int i = 0; i < 4; i++) {
        int v = (base + i < V) ? base + i : V - 1;
        n[i] = N2[(size_t)v * 32 + lane];
    }
    float2 a[4] = {{0,0},{0,0},{0,0},{0,0}};
    const float2* W2 = (const float2*)sW;
    #pragma unroll
    for (int kk = 0; kk < 32; kk++) {
        float2 w0 = W2[(2 * kk) * 32 + lane];
        float2 w1 = W2[(2 * kk + 1) * 32 + lane];
        #pragma unroll
        for (int i = 0; i < 4; i++) {
            float xk0 = __shfl_sync(0xffffffffu, n[i].x, kk);
            float xk1 = __shfl_sync(0xffffffffu, n[i].y, kk);
            a[i].x += xk0 * w0.x + xk1 * w1.x;
            a[i].y += xk0 * w0.y + xk1 * w1.y;
        }
    }
    float2 w2v = sw2[lane];
    #pragma unroll
    for (int i = 0; i < 4; i++) {
        float e = tanh_fast(a[i].x) * w2v.x + tanh_fast(a[i].y) * w2v.y;
        #pragma unroll
        for (int o = 16; o > 0; o >>= 1) e += __shfl_xor_sync(0xffffffffu, e, o);
        float w = expf(e);
        int v = base + i;
        if (v < V) {
            if (lane == 0) wOut[v] = w;
            WN[(size_t)v * 32 + lane] = __float22half2_rn(make_float2(w * n[i].x, w * n[i].y));
        }
    }
}

// ---------------- phase1: fused histogram (4 graphs) + node scores -----------------
__global__ __launch_bounds__(256) void phase1_kernel(
    const int* __restrict__ d0, int e0, const int* __restrict__ d1, int e1,
    const int* __restrict__ d2, int e2, const int* __restrict__ d3, int e3, int CB,
    const float* __restrict__ localN, const float* __restrict__ globalN,
    const float* __restrict__ lW1, const float* __restrict__ lw2,
    const float* __restrict__ gW1, const float* __restrict__ gw2, int V, int SB)
{
    if ((int)blockIdx.x < CB) {
        // ---- count path ----
        int i = blockIdx.x * blockDim.x + threadIdx.x;
        int g, j;
        if (i < e0)                     { g = 0; j = i; }
        else if (i < e0 + e1)           { g = 1; j = i - e0; }
        else if (i < e0 + e1 + e2)      { g = 2; j = i - e0 - e1; }
        else if (i < e0 + e1 + e2 + e3) { g = 3; j = i - e0 - e1 - e2; }
        else return;
        const int* d = (g == 0) ? d0 : (g == 1) ? d1 : (g == 2) ? d2 : d3;
        atomicAdd(&g_cnt[g * V_MAX + d[j]], 1);
        return;
    }
    // ---- scores path (grid-resident: SB blocks, warps stride over nodes) ----
    __shared__ float sWl[D * D];
    __shared__ float sWg[D * D];
    __shared__ float2 swl[32];
    __shared__ float2 swg[32];
    for (int i = threadIdx.x; i < D * D; i += blockDim.x) { sWl[i] = lW1[i]; sWg[i] = gW1[i]; }
    for (int i = threadIdx.x; i < 32; i += blockDim.x) {
        swl[i] = ((const float2*)lw2)[i];
        swg[i] = ((const float2*)gw2)[i];
    }
    __syncthreads();

    int lane = threadIdx.x & 31;
    int grp  = ((blockIdx.x - CB) * blockDim.x + threadIdx.x) >> 5;
    int ngrp = SB * 8;

    for (int base = grp * 4; base < V; base += ngrp * 4) {
        score4((const float2*)localN,  sWl, swl, g_wL, g_WNL, base, V, lane);
        score4((const float2*)globalN, sWg, swg, g_wG, g_WNG, base, V, lane);
    }
}

// ---------------- scan helpers ----------------------------------------------------
__device__ __forceinline__ int block_incl_scan(int x, int tid, int* ws) {
    int lane = tid & 31, wid = tid >> 5;
    #pragma unroll
    for (int o = 1; o < 32; o <<= 1) {
        int y = __shfl_up_sync(0xffffffffu, x, o);
        if (lane >= o) x += y;
    }
    if (lane == 31) ws[wid] = x;
    __syncthreads();
    if (wid == 0) {
        int v = (lane < 8) ? ws[lane] : 0;
        #pragma unroll
        for (int o = 1; o < 8; o <<= 1) {
            int y = __shfl_up_sync(0xffffffffu, v, o);
            if (lane >= o) v += y;
        }
        if (lane < 8) ws[lane] = v;
    }
    __syncthreads();
    if (wid > 0) x += ws[wid - 1];
    return x;
}

__global__ __launch_bounds__(256) void scan1_kernel(int V) {
    __shared__ int ws[8];
    int g = blockIdx.y, b = blockIdx.x, tid = threadIdx.x;
    int base = b * 1024 + tid * 4;
    int s = 0;
    #pragma unroll
    for (int j = 0; j < 4; j++) { int i = base + j; if (i < V) s += g_cnt[g * V_MAX + i]; }
    int incl = block_incl_scan(s, tid, ws);
    if (tid == 255) g_bsum[g * NBMAX + b] = incl;
}

__global__ __launch_bounds__(128) void scan2_kernel(int V) {
    __shared__ int ws[8];
    int g = blockIdx.x, t = threadIdx.x;
    int x = g_bsum[g * NBMAX + t];
    int orig = x;
    int incl = block_incl_scan(x, t, ws);
    g_bsum[g * NBMAX + t] = incl - orig;
    if (t == 127) g_off[g * (V_MAX + 1) + V] = incl;
}

__global__ __launch_bounds__(256) void scan3_kernel(int V) {
    __shared__ int ws[8];
    int g = blockIdx.y, b = blockIdx.x, tid = threadIdx.x;
    int base = b * 1024 + tid * 4;
    int c[4]; int s = 0;
    #pragma unroll
    for (int j = 0; j < 4; j++) {
        int i = base + j;
        c[j] = (i < V) ? g_cnt[g * V_MAX + i] : 0;
        s += c[j];
    }
    int incl = block_incl_scan(s, tid, ws);
    int p = g_bsum[g * NBMAX + b] + incl - s;
    #pragma unroll
    for (int j = 0; j < 4; j++) {
        int i = base + j;
        if (i < V) { g_off[g * (V_MAX + 1) + i] = p; g_cur[g * V_MAX + i] = p; p += c[j]; }
    }
}

// ---------------- fused scatter over 4 graphs --------------------------------------
__global__ __launch_bounds__(256) void scatter_kernel(
    const int* __restrict__ d0, const int* __restrict__ s0, int e0,
    const int* __restrict__ d1, const int* __restrict__ s1, int e1,
    const int* __restrict__ d2, int e2,
    const int* __restrict__ d3, int e3)
{
    int i = blockIdx.x * blockDim.x + threadIdx.x;
    int g, j;
    if (i < e0)                     { g = 0; j = i; }
    else if (i < e0 + e1)           { g = 1; j = i - e0; }
    else if (i < e0 + e1 + e2)      { g = 2; j = i - e0 - e1; }
    else if (i < e0 + e1 + e2 + e3) { g = 3; j = i - e0 - e1 - e2; }
    else return;
    int dst, payload; int* bin;
    if (g == 0)      { dst = d0[j]; payload = s0[j]; bin = g_binNG; }
    else if (g == 1) { dst = d1[j]; payload = s1[j]; bin = g_binLOC; }
    else if (g == 2) { dst = d2[j]; payload = j;     bin = g_binI; }
    else             { dst = d3[j]; payload = j;     bin = g_binS; }
    int p = atomicAdd(&g_cur[g * V_MAX + dst], 1);
    bin[p] = payload;
}

// ---------------- gather helpers (batched index, MLP-4 rows) -----------------------
__device__ __forceinline__ void gat_gather(
    const int* __restrict__ bin, int e, int eEnd,
    const __half2* __restrict__ WN, const float* __restrict__ w,
    int lane, float2& acc)
{
    float ax0 = 0.f, ay0 = 0.f, ax1 = 0.f, ay1 = 0.f, denp = 0.f;
    for (int base = e; base < eEnd; base += 32) {
        int n = eEnd - base; if (n > 32) n = 32;
        int idx = 0; float wv = 0.f;
        if (lane < n) { idx = bin[base + lane]; wv = __ldg(w + idx); }
        denp += wv;
        int j = 0;
        for (; j + 4 <= n; j += 4) {
            int s0 = __shfl_sync(0xffffffffu, idx, j);
            int s1 = __shfl_sync(0xffffffffu, idx, j + 1);
            int s2 = __shfl_sync(0xffffffffu, idx, j + 2);
            int s3 = __shfl_sync(0xffffffffu, idx, j + 3);
            float2 x0 = __half22float2(__ldg(WN + (size_t)s0 * 32 + lane));
            float2 x1 = __half22float2(__ldg(WN + (size_t)s1 * 32 + lane));
            float2 x2 = __half22float2(__ldg(WN + (size_t)s2 * 32 + lane));
            float2 x3 = __half22float2(__ldg(WN + (size_t)s3 * 32 + lane));
            ax0 += x0.x + x1.x; ay0 += x0.y + x1.y;
            ax1 += x2.x + x3.x; ay1 += x2.y + x3.y;
        }
        for (; j < n; j++) {
            int s0 = __shfl_sync(0xffffffffu, idx, j);
            float2 x0 = __half22float2(__ldg(WN + (size_t)s0 * 32 + lane));
            ax0 += x0.x; ay0 += x0.y;
        }
    }
    #pragma unroll
    for (int o = 16; o > 0; o >>= 1) denp += __shfl_xor_sync(0xffffffffu, denp, o);
    float inv = denp > 0.f ? 1.f / denp : 1.f;
    acc = make_float2((ax0 + ax1) * inv, (ay0 + ay1) * inv);
}

__device__ __forceinline__ void mean_gather(
    const int* __restrict__ bin, int e, int eEnd,
    const float2* __restrict__ E2, int lane, float2& acc)
{
    int cnt = eEnd - e;
    float ax0 = 0.f, ay0 = 0.f, ax1 = 0.f, ay1 = 0.f;
    for (int base = e; base < eEnd; base += 32) {
        int n = eEnd - base; if (n > 32) n = 32;
        int idx = 0;
        if (lane < n) idx = bin[base + lane];
        int j = 0;
        for (; j + 4 <= n; j += 4) {
            int s0 = __shfl_sync(0xffffffffu, idx, j);
            int s1 = __shfl_sync(0xffffffffu, idx, j + 1);
            int s2 = __shfl_sync(0xffffffffu, idx, j + 2);
            int s3 = __shfl_sync(0xffffffffu, idx, j + 3);
            float2 x0 = __ldg(E2 + (size_t)s0 * 32 + lane);
            float2 x1 = __ldg(E2 + (size_t)s1 * 32 + lane);
            float2 x2 = __ldg(E2 + (size_t)s2 * 32 + lane);
            float2 x3 = __ldg(E2 + (size_t)s3 * 32 + lane);
            ax0 += x0.x + x1.x; ay0 += x0.y + x1.y;
            ax1 += x2.x + x3.x; ay1 += x2.y + x3.y;
        }
        for (; j < n; j++) {
            int s0 = __shfl_sync(0xffffffffu, idx, j);
            float2 x0 = __ldg(E2 + (size_t)s0 * 32 + lane);
            ax0 += x0.x; ay0 += x0.y;
        }
    }
    float inv = cnt > 0 ? 1.f / (float)cnt : 1.f;
    acc = make_float2((ax0 + ax1) * inv, (ay0 + ay1) * inv);
}

// ---------------- mega node kernel (grid-resident): gathers + attention + output ----
__global__ __launch_bounds__(256) void node_kernel(
    float* __restrict__ out, const float* __restrict__ edge_E, int E_INT,
    const float* __restrict__ Ws,
    const float* __restrict__ eW1, const float* __restrict__ ew2,
    const float* __restrict__ eW3, int V, int NB)
{
    __shared__ float sW1[D * D];
    __shared__ float sW3[D * D];
    __shared__ float2 sw2[32];
    for (int i = threadIdx.x; i < D * D; i += blockDim.x) { sW1[i] = eW1[i]; sW3[i] = eW3[i]; }
    for (int i = threadIdx.x; i < 32; i += blockDim.x) sw2[i] = ((const float2*)ew2)[i];
    __syncthreads();

    int warp   = (blockIdx.x * blockDim.x + threadIdx.x) >> 5;
    int lane   = threadIdx.x & 31;
    int nwarps = NB * 8;

    const int* offNG  = g_off + 0 * (V_MAX + 1);
    const int* offLOC = g_off + 1 * (V_MAX + 1);
    const int* offI   = g_off + 2 * (V_MAX + 1);
    const int* offS   = g_off + 3 * (V_MAX + 1);

    float2* out2 = (float2*)out;
    const float2* W1_2 = (const float2*)sW1;
    const float2* W3_2 = (const float2*)sW3;

    for (int v = warp; v < V; v += nwarps) {
        // local GAT -> out[:, 0:64]
        {
            float2 lacc;
            gat_gather(g_binLOC, offLOC[v], offLOC[v + 1], g_WNL, g_wL, lane, lacc);
            out2[(size_t)v * 64 + lane] = lacc;
        }

        // ng GAT
        float2 np;
        gat_gather(g_binNG, offNG[v], offNG[v + 1], g_WNG, g_wG, lane, np);

        // means
        float2 yi, ys;
        mean_gather(g_binI, offI[v], offI[v + 1], (const float2*)edge_E, lane, yi);
        mean_gather(g_binS, offS[v], offS[v + 1],
                    (const float2*)(edge_E + (size_t)E_INT * D), lane, ys);

        // a = yi @ eW1, b = ys @ eW1 (interleaved)
        float2 a = make_float2(0.f, 0.f), b = make_float2(0.f, 0.f);
        #pragma unroll
        for (int kk = 0; kk < 32; kk++) {
            float2 w0 = W1_2[(2 * kk) * 32 + lane];
            float2 w1 = W1_2[(2 * kk + 1) * 32 + lane];
            float yi0 = __shfl_sync(0xffffffffu, yi.x, kk);
            float yi1 = __shfl_sync(0xffffffffu, yi.y, kk);
            float ys0 = __shfl_sync(0xffffffffu, ys.x, kk);
            float ys1 = __shfl_sync(0xffffffffu, ys.y, kk);
            a.x += yi0 * w0.x + yi1 * w1.x;
            a.y += yi0 * w0.y + yi1 * w1.y;
            b.x += ys0 * w0.x + ys1 * w1.x;
            b.y += ys0 * w0.y + ys1 * w1.y;
        }
        float2 w2v = sw2[lane];
        float eI = tanhf(a.x) * w2v.x + tanhf(a.y) * w2v.y;
        float eS = tanhf(b.x) * w2v.x + tanhf(b.y) * w2v.y;
        #pragma unroll
        for (int o = 16; o > 0; o >>= 1) {
            eI += __shfl_xor_sync(0xffffffffu, eI, o);
            eS += __shfl_xor_sync(0xffffffffu, eS, o);
        }
        float mx = fmaxf(eI, eS);
        float u0 = expf(eI - mx), u1 = expf(eS - mx);
        float inv = 1.f / (u0 + u1);
        float A0 = u0 * inv, A1 = u1 * inv;
        float2 oy = make_float2(A0 * yi.x + A1 * ys.x, A0 * yi.y + A1 * ys.y);

        // Fg = oy @ eW3
        float2 f = make_float2(0.f, 0.f);
        #pragma unroll
        for (int kk = 0; kk < 32; kk++) {
            float2 w0 = W3_2[(2 * kk) * 32 + lane];
            float2 w1 = W3_2[(2 * kk + 1) * 32 + lane];
            float o0 = __shfl_sync(0xffffffffu, oy.x, kk);
            float o1 = __shfl_sync(0xffffffffu, oy.y, kk);
            f.x += o0 * w0.x + o1 * w1.x;
            f.y += o0 * w0.y + o1 * w1.y;
        }

        float2 wsv = ((const float2*)Ws)[(size_t)v * 32 + lane];
        out2[(size_t)v * 64 + 32 + lane] = make_float2(wsv.x * f.x + np.x, wsv.y * f.y + np.y);
    }
}

// ---------------- launch ---------------------------------------------------------
extern "C" void kernel_launch(void* const* d_in, const int* in_sizes, int n_in,
                              void* d_out, int out_size)
{
    const float* local_N  = (const float*)d_in[0];
    const float* global_N = (const float*)d_in[1];
    const float* edge_E   = (const float*)d_in[2];
    const float* Ws       = (const float*)d_in[3];
    const float* lW1      = (const float*)d_in[4];
    const float* lw2      = (const float*)d_in[5];
    const float* gW1      = (const float*)d_in[6];
    const float* gw2      = (const float*)d_in[7];
    const float* eW1      = (const float*)d_in[8];
    const float* ew2      = (const float*)d_in[9];
    const float* eW3      = (const float*)d_in[10];
    const int* ng_src     = (const int*)d_in[11];
    const int* ng_dst     = (const int*)d_in[12];
    const int* local_src  = (const int*)d_in[13];
    const int* local_dst  = (const int*)d_in[14];
    const int* int_dst    = (const int*)d_in[16];
    const int* sim_dst    = (const int*)d_in[18];

    const int V      = in_sizes[0] / D;
    const int E_NG   = in_sizes[11];
    const int E_LOC  = in_sizes[13];
    const int E_INT  = in_sizes[15];
    const int E_SIM  = in_sizes[17];
    const int E_ALL  = E_NG + E_LOC + E_INT + E_SIM;

    float* out = (float*)d_out;

    int* pCnt;
    cudaGetSymbolAddress((void**)&pCnt, g_cnt);

    // zero counts
    cudaMemsetAsync(pCnt, 0, 4 * V_MAX * sizeof(int));

    // phase1: fused count + scores (scores grid-resident: 592 blocks)
    int CB = (E_ALL + 255) / 256;
    int SB = 592;
    phase1_kernel<<<CB + SB, 256>>>(ng_dst, E_NG, local_dst, E_LOC,
                                    int_dst, E_INT, sim_dst, E_SIM, CB,
                                    local_N, global_N, lW1, lw2, gW1, gw2, V, SB);

    // scans
    dim3 sgrid(NBMAX, 4);
    scan1_kernel<<<sgrid, 256>>>(V);
    scan2_kernel<<<4, 128>>>(V);
    scan3_kernel<<<sgrid, 256>>>(V);

    // scatter
    scatter_kernel<<<(E_ALL + 255) / 256, 256>>>(ng_dst, ng_src, E_NG,
                                                 local_dst, local_src, E_LOC,
                                                 int_dst, E_INT, sim_dst, E_SIM);

    // fused per-node gathers + attention + output (grid-resident)
    int NB = 1184;
    node_kernel<<<NB, 256>>>(out, edge_E, E_INT, Ws, eW1, ew2, eW3, V, NB);
}

// round 8
// speedup vs baseline: 1.1038x; 1.1038x over previous
#include <cuda_runtime.h>
#include <cuda_fp16.h>
#include <math.h>

#define D 64
#define V_MAX 100000
#define NBMAX 128
#define E_NG_MAX  2000000
#define E_LOC_MAX 1000000
#define E_INT_MAX 1200000
#define E_SIM_MAX  800000

// ---------------- scratch ------------------------------------------------------
__device__ float   g_wL[V_MAX];
__device__ float   g_wG[V_MAX];
__device__ __half2 g_WNL[V_MAX * 32];
__device__ __half2 g_WNG[V_MAX * 32];

__device__ int g_cnt[4 * V_MAX];
__device__ int g_off[4 * (V_MAX + 1)];
__device__ int g_cur[4 * V_MAX];
__device__ int g_bsum[4 * NBMAX];
__device__ int g_binNG[E_NG_MAX];
__device__ int g_binLOC[E_LOC_MAX];
__device__ int g_binI[E_INT_MAX];
__device__ int g_binS[E_SIM_MAX];

__device__ __forceinline__ float tanh_fast(float x) {
    float r;
    asm("tanh.approx.f32 %0, %1;" : "=f"(r) : "f"(x));
    return r;
}

// ---------------- scores helper (interleaved float2 layout, 4 nodes/warp) ----------
__device__ __forceinline__ void score4(
    const float2* __restrict__ N2, const float* __restrict__ sW,
    const float2* __restrict__ sw2, float* __restrict__ wOut,
    __half2* __restrict__ WN, int base, int V, int lane)
{
    float2 n[4];
    #pragma unroll
    for (int i = 0; i < 4; i++) {
        int v = (base + i < V) ? base + i : V - 1;
        n[i] = N2[(size_t)v * 32 + lane];
    }
    float2 a[4] = {{0,0},{0,0},{0,0},{0,0}};
    const float2* W2 = (const float2*)sW;
    #pragma unroll
    for (int kk = 0; kk < 32; kk++) {
        float2 w0 = W2[(2 * kk) * 32 + lane];
        float2 w1 = W2[(2 * kk + 1) * 32 + lane];
        #pragma unroll
        for (int i = 0; i < 4; i++) {
            float xk0 = __shfl_sync(0xffffffffu, n[i].x, kk);
            float xk1 = __shfl_sync(0xffffffffu, n[i].y, kk);
            a[i].x += xk0 * w0.x + xk1 * w1.x;
            a[i].y += xk0 * w0.y + xk1 * w1.y;
        }
    }
    float2 w2v = sw2[lane];
    #pragma unroll
    for (int i = 0; i < 4; i++) {
        float e = tanh_fast(a[i].x) * w2v.x + tanh_fast(a[i].y) * w2v.y;
        #pragma unroll
        for (int o = 16; o > 0; o >>= 1) e += __shfl_xor_sync(0xffffffffu, e, o);
        float w = expf(e);
        int v = base + i;
        if (v < V) {
            if (lane == 0) wOut[v] = w;
            WN[(size_t)v * 32 + lane] = __float22half2_rn(make_float2(w * n[i].x, w * n[i].y));
        }
    }
}

// ---------------- phase1: fused histogram (4 graphs) + node scores -----------------
__global__ __launch_bounds__(256) void phase1_kernel(
    const int* __restrict__ d0, int e0, const int* __restrict__ d1, int e1,
    const int* __restrict__ d2, int e2, const int* __restrict__ d3, int e3, int CB,
    const float* __restrict__ localN, const float* __restrict__ globalN,
    const float* __restrict__ lW1, const float* __restrict__ lw2,
    const float* __restrict__ gW1, const float* __restrict__ gw2, int V, int SB)
{
    if ((int)blockIdx.x < CB) {
        int i = blockIdx.x * blockDim.x + threadIdx.x;
        int g, j;
        if (i < e0)                     { g = 0; j = i; }
        else if (i < e0 + e1)           { g = 1; j = i - e0; }
        else if (i < e0 + e1 + e2)      { g = 2; j = i - e0 - e1; }
        else if (i < e0 + e1 + e2 + e3) { g = 3; j = i - e0 - e1 - e2; }
        else return;
        const int* d = (g == 0) ? d0 : (g == 1) ? d1 : (g == 2) ? d2 : d3;
        atomicAdd(&g_cnt[g * V_MAX + d[j]], 1);
        return;
    }
    __shared__ float sWl[D * D];
    __shared__ float sWg[D * D];
    __shared__ float2 swl[32];
    __shared__ float2 swg[32];
    for (int i = threadIdx.x; i < D * D; i += blockDim.x) { sWl[i] = lW1[i]; sWg[i] = gW1[i]; }
    for (int i = threadIdx.x; i < 32; i += blockDim.x) {
        swl[i] = ((const float2*)lw2)[i];
        swg[i] = ((const float2*)gw2)[i];
    }
    __syncthreads();

    int lane = threadIdx.x & 31;
    int grp  = ((blockIdx.x - CB) * blockDim.x + threadIdx.x) >> 5;
    int ngrp = SB * 8;

    for (int base = grp * 4; base < V; base += ngrp * 4) {
        score4((const float2*)localN,  sWl, swl, g_wL, g_WNL, base, V, lane);
        score4((const float2*)globalN, sWg, swg, g_wG, g_WNG, base, V, lane);
    }
}

// ---------------- scan helpers ----------------------------------------------------
__device__ __forceinline__ int block_incl_scan(int x, int tid, int* ws) {
    int lane = tid & 31, wid = tid >> 5;
    #pragma unroll
    for (int o = 1; o < 32; o <<= 1) {
        int y = __shfl_up_sync(0xffffffffu, x, o);
        if (lane >= o) x += y;
    }
    if (lane == 31) ws[wid] = x;
    __syncthreads();
    if (wid == 0) {
        int v = (lane < 8) ? ws[lane] : 0;
        #pragma unroll
        for (int o = 1; o < 8; o <<= 1) {
            int y = __shfl_up_sync(0xffffffffu, v, o);
            if (lane >= o) v += y;
        }
        if (lane < 8) ws[lane] = v;
    }
    __syncthreads();
    if (wid > 0) x += ws[wid - 1];
    return x;
}

__global__ __launch_bounds__(256) void scan1_kernel(int V) {
    __shared__ int ws[8];
    int g = blockIdx.y, b = blockIdx.x, tid = threadIdx.x;
    int base = b * 1024 + tid * 4;
    int s = 0;
    #pragma unroll
    for (int j = 0; j < 4; j++) { int i = base + j; if (i < V) s += g_cnt[g * V_MAX + i]; }
    int incl = block_incl_scan(s, tid, ws);
    if (tid == 255) g_bsum[g * NBMAX + b] = incl;
}

__global__ __launch_bounds__(128) void scan2_kernel(int V) {
    __shared__ int ws[8];
    int g = blockIdx.x, t = threadIdx.x;
    int x = g_bsum[g * NBMAX + t];
    int orig = x;
    int incl = block_incl_scan(x, t, ws);
    g_bsum[g * NBMAX + t] = incl - orig;
    if (t == 127) g_off[g * (V_MAX + 1) + V] = incl;
}

__global__ __launch_bounds__(256) void scan3_kernel(int V) {
    __shared__ int ws[8];
    int g = blockIdx.y, b = blockIdx.x, tid = threadIdx.x;
    int base = b * 1024 + tid * 4;
    int c[4]; int s = 0;
    #pragma unroll
    for (int j = 0; j < 4; j++) {
        int i = base + j;
        c[j] = (i < V) ? g_cnt[g * V_MAX + i] : 0;
        s += c[j];
    }
    int incl = block_incl_scan(s, tid, ws);
    int p = g_bsum[g * NBMAX + b] + incl - s;
    #pragma unroll
    for (int j = 0; j < 4; j++) {
        int i = base + j;
        if (i < V) { g_off[g * (V_MAX + 1) + i] = p; g_cur[g * V_MAX + i] = p; p += c[j]; }
    }
}

// ---------------- fused scatter over 4 graphs --------------------------------------
__global__ __launch_bounds__(256) void scatter_kernel(
    const int* __restrict__ d0, const int* __restrict__ s0, int e0,
    const int* __restrict__ d1, const int* __restrict__ s1, int e1,
    const int* __restrict__ d2, int e2,
    const int* __restrict__ d3, int e3)
{
    int i = blockIdx.x * blockDim.x + threadIdx.x;
    int g, j;
    if (i < e0)                     { g = 0; j = i; }
    else if (i < e0 + e1)           { g = 1; j = i - e0; }
    else if (i < e0 + e1 + e2)      { g = 2; j = i - e0 - e1; }
    else if (i < e0 + e1 + e2 + e3) { g = 3; j = i - e0 - e1 - e2; }
    else return;
    int dst, payload; int* bin;
    if (g == 0)      { dst = d0[j]; payload = s0[j]; bin = g_binNG; }
    else if (g == 1) { dst = d1[j]; payload = s1[j]; bin = g_binLOC; }
    else if (g == 2) { dst = d2[j]; payload = j;     bin = g_binI; }
    else             { dst = d3[j]; payload = j;     bin = g_binS; }
    int p = atomicAdd(&g_cur[g * V_MAX + dst], 1);
    bin[p] = payload;
}

// ---------------- dual-node gather helpers (2 independent chains per warp) ---------
__device__ __forceinline__ void gat_gather2(
    const int* __restrict__ bin, int eA, int endA, int eB, int endB,
    const __half2* __restrict__ WN, const float* __restrict__ w,
    int lane, float2& accA, float2& accB)
{
    float axA = 0.f, ayA = 0.f, dA = 0.f;
    float axB = 0.f, ayB = 0.f, dB = 0.f;
    while (eA + 2 <= endA && eB + 2 <= endB) {
        int sA0 = bin[eA], sA1 = bin[eA + 1];
        int sB0 = bin[eB], sB1 = bin[eB + 1];
        float2 xA0 = __half22float2(__ldg(WN + (size_t)sA0 * 32 + lane));
        float2 xB0 = __half22float2(__ldg(WN + (size_t)sB0 * 32 + lane));
        float2 xA1 = __half22float2(__ldg(WN + (size_t)sA1 * 32 + lane));
        float2 xB1 = __half22float2(__ldg(WN + (size_t)sB1 * 32 + lane));
        float wA0 = __ldg(w + sA0), wA1 = __ldg(w + sA1);
        float wB0 = __ldg(w + sB0), wB1 = __ldg(w + sB1);
        axA += xA0.x + xA1.x; ayA += xA0.y + xA1.y; dA += wA0 + wA1;
        axB += xB0.x + xB1.x; ayB += xB0.y + xB1.y; dB += wB0 + wB1;
        eA += 2; eB += 2;
    }
    while (eA + 2 <= endA) {
        int s0 = bin[eA], s1 = bin[eA + 1];
        float2 x0 = __half22float2(__ldg(WN + (size_t)s0 * 32 + lane));
        float2 x1 = __half22float2(__ldg(WN + (size_t)s1 * 32 + lane));
        axA += x0.x + x1.x; ayA += x0.y + x1.y; dA += __ldg(w + s0) + __ldg(w + s1);
        eA += 2;
    }
    while (eB + 2 <= endB) {
        int s0 = bin[eB], s1 = bin[eB + 1];
        float2 x0 = __half22float2(__ldg(WN + (size_t)s0 * 32 + lane));
        float2 x1 = __half22float2(__ldg(WN + (size_t)s1 * 32 + lane));
        axB += x0.x + x1.x; ayB += x0.y + x1.y; dB += __ldg(w + s0) + __ldg(w + s1);
        eB += 2;
    }
    if (eA < endA) {
        int s = bin[eA];
        float2 x = __half22float2(__ldg(WN + (size_t)s * 32 + lane));
        axA += x.x; ayA += x.y; dA += __ldg(w + s);
    }
    if (eB < endB) {
        int s = bin[eB];
        float2 x = __half22float2(__ldg(WN + (size_t)s * 32 + lane));
        axB += x.x; ayB += x.y; dB += __ldg(w + s);
    }
    float iA = dA > 0.f ? 1.f / dA : 1.f;
    float iB = dB > 0.f ? 1.f / dB : 1.f;
    accA = make_float2(axA * iA, ayA * iA);
    accB = make_float2(axB * iB, ayB * iB);
}

__device__ __forceinline__ void mean_gather2(
    const int* __restrict__ bin, int eA, int endA, int eB, int endB,
    const float2* __restrict__ E2, int lane, float2& accA, float2& accB)
{
    int cA = endA - eA, cB = endB - eB;
    float axA = 0.f, ayA = 0.f, axB = 0.f, ayB = 0.f;
    while (eA + 2 <= endA && eB + 2 <= endB) {
        int sA0 = bin[eA], sA1 = bin[eA + 1];
        int sB0 = bin[eB], sB1 = bin[eB + 1];
        float2 xA0 = __ldg(E2 + (size_t)sA0 * 32 + lane);
        float2 xB0 = __ldg(E2 + (size_t)sB0 * 32 + lane);
        float2 xA1 = __ldg(E2 + (size_t)sA1 * 32 + lane);
        float2 xB1 = __ldg(E2 + (size_t)sB1 * 32 + lane);
        axA += xA0.x + xA1.x; ayA += xA0.y + xA1.y;
        axB += xB0.x + xB1.x; ayB += xB0.y + xB1.y;
        eA += 2; eB += 2;
    }
    while (eA + 2 <= endA) {
        int s0 = bin[eA], s1 = bin[eA + 1];
        float2 x0 = __ldg(E2 + (size_t)s0 * 32 + lane);
        float2 x1 = __ldg(E2 + (size_t)s1 * 32 + lane);
        axA += x0.x + x1.x; ayA += x0.y + x1.y;
        eA += 2;
    }
    while (eB + 2 <= endB) {
        int s0 = bin[eB], s1 = bin[eB + 1];
        float2 x0 = __ldg(E2 + (size_t)s0 * 32 + lane);
        float2 x1 = __ldg(E2 + (size_t)s1 * 32 + lane);
        axB += x0.x + x1.x; ayB += x0.y + x1.y;
        eB += 2;
    }
    if (eA < endA) {
        float2 x = __ldg(E2 + (size_t)bin[eA] * 32 + lane);
        axA += x.x; ayA += x.y;
    }
    if (eB < endB) {
        float2 x = __ldg(E2 + (size_t)bin[eB] * 32 + lane);
        axB += x.x; ayB += x.y;
    }
    float iA = cA > 0 ? 1.f / (float)cA : 1.f;
    float iB = cB > 0 ? 1.f / (float)cB : 1.f;
    accA = make_float2(axA * iA, ayA * iA);
    accB = make_float2(axB * iB, ayB * iB);
}

// ---------------- mega node kernel: 2 nodes per warp --------------------------------
__global__ __launch_bounds__(256) void node_kernel(
    float* __restrict__ out, const float* __restrict__ edge_E, int E_INT,
    const float* __restrict__ Ws,
    const float* __restrict__ eW1, const float* __restrict__ ew2,
    const float* __restrict__ eW3, int V)
{
    __shared__ float sW1[D * D];
    __shared__ float sW3[D * D];
    __shared__ float2 sw2[32];
    for (int i = threadIdx.x; i < D * D; i += blockDim.x) { sW1[i] = eW1[i]; sW3[i] = eW3[i]; }
    for (int i = threadIdx.x; i < 32; i += blockDim.x) sw2[i] = ((const float2*)ew2)[i];
    __syncthreads();

    int pair = (blockIdx.x * blockDim.x + threadIdx.x) >> 5;
    int lane = threadIdx.x & 31;
    int v0 = pair * 2;
    if (v0 >= V) return;
    int v1 = v0 + 1;
    bool hasB = v1 < V;
    int v1c = hasB ? v1 : v0;

    const int* offNG  = g_off + 0 * (V_MAX + 1);
    const int* offLOC = g_off + 1 * (V_MAX + 1);
    const int* offI   = g_off + 2 * (V_MAX + 1);
    const int* offS   = g_off + 3 * (V_MAX + 1);

    float2* out2 = (float2*)out;
    const float2* W1_2 = (const float2*)sW1;
    const float2* W3_2 = (const float2*)sW3;

    // local GAT -> out[:, 0:64]
    {
        float2 lA, lB;
        gat_gather2(g_binLOC, offLOC[v0], offLOC[v0 + 1], offLOC[v1c], offLOC[v1c + 1],
                    g_WNL, g_wL, lane, lA, lB);
        out2[(size_t)v0 * 64 + lane] = lA;
        if (hasB) out2[(size_t)v1 * 64 + lane] = lB;
    }

    // ng GAT
    float2 np[2];
    gat_gather2(g_binNG, offNG[v0], offNG[v0 + 1], offNG[v1c], offNG[v1c + 1],
                g_WNG, g_wG, lane, np[0], np[1]);

    // means
    float2 yi[2], ys[2];
    mean_gather2(g_binI, offI[v0], offI[v0 + 1], offI[v1c], offI[v1c + 1],
                 (const float2*)edge_E, lane, yi[0], yi[1]);
    mean_gather2(g_binS, offS[v0], offS[v0 + 1], offS[v1c], offS[v1c + 1],
                 (const float2*)(edge_E + (size_t)E_INT * D), lane, ys[0], ys[1]);

    // attention matvecs, both nodes sharing weight loads
    float2 a[2] = {{0,0},{0,0}}, b[2] = {{0,0},{0,0}};
    #pragma unroll
    for (int kk = 0; kk < 32; kk++) {
        float2 w0 = W1_2[(2 * kk) * 32 + lane];
        float2 w1 = W1_2[(2 * kk + 1) * 32 + lane];
        #pragma unroll
        for (int i = 0; i < 2; i++) {
            float yi0 = __shfl_sync(0xffffffffu, yi[i].x, kk);
            float yi1 = __shfl_sync(0xffffffffu, yi[i].y, kk);
            float ys0 = __shfl_sync(0xffffffffu, ys[i].x, kk);
            float ys1 = __shfl_sync(0xffffffffu, ys[i].y, kk);
            a[i].x += yi0 * w0.x + yi1 * w1.x;
            a[i].y += yi0 * w0.y + yi1 * w1.y;
            b[i].x += ys0 * w0.x + ys1 * w1.x;
            b[i].y += ys0 * w0.y + ys1 * w1.y;
        }
    }
    float2 w2v = sw2[lane];
    float2 oy[2];
    #pragma unroll
    for (int i = 0; i < 2; i++) {
        float eI = tanhf(a[i].x) * w2v.x + tanhf(a[i].y) * w2v.y;
        float eS = tanhf(b[i].x) * w2v.x + tanhf(b[i].y) * w2v.y;
        #pragma unroll
        for (int o = 16; o > 0; o >>= 1) {
            eI += __shfl_xor_sync(0xffffffffu, eI, o);
            eS += __shfl_xor_sync(0xffffffffu, eS, o);
        }
        float mx = fmaxf(eI, eS);
        float u0 = expf(eI - mx), u1 = expf(eS - mx);
        float inv = 1.f / (u0 + u1);
        oy[i] = make_float2(u0 * inv * yi[i].x + u1 * inv * ys[i].x,
                            u0 * inv * yi[i].y + u1 * inv * ys[i].y);
    }

    float2 f[2] = {{0,0},{0,0}};
    #pragma unroll
    for (int kk = 0; kk < 32; kk++) {
        float2 w0 = W3_2[(2 * kk) * 32 + lane];
        float2 w1 = W3_2[(2 * kk + 1) * 32 + lane];
        #pragma unroll
        for (int i = 0; i < 2; i++) {
            float o0 = __shfl_sync(0xffffffffu, oy[i].x, kk);
            float o1 = __shfl_sync(0xffffffffu, oy[i].y, kk);
            f[i].x += o0 * w0.x + o1 * w1.x;
            f[i].y += o0 * w0.y + o1 * w1.y;
        }
    }

    {
        float2 wsv = ((const float2*)Ws)[(size_t)v0 * 32 + lane];
        out2[(size_t)v0 * 64 + 32 + lane] =
            make_float2(wsv.x * f[0].x + np[0].x, wsv.y * f[0].y + np[0].y);
    }
    if (hasB) {
        float2 wsv = ((const float2*)Ws)[(size_t)v1 * 32 + lane];
        out2[(size_t)v1 * 64 + 32 + lane] =
            make_float2(wsv.x * f[1].x + np[1].x, wsv.y * f[1].y + np[1].y);
    }
}

// ---------------- launch ---------------------------------------------------------
extern "C" void kernel_launch(void* const* d_in, const int* in_sizes, int n_in,
                              void* d_out, int out_size)
{
    const float* local_N  = (const float*)d_in[0];
    const float* global_N = (const float*)d_in[1];
    const float* edge_E   = (const float*)d_in[2];
    const float* Ws       = (const float*)d_in[3];
    const float* lW1      = (const float*)d_in[4];
    const float* lw2      = (const float*)d_in[5];
    const float* gW1      = (const float*)d_in[6];
    const float* gw2      = (const float*)d_in[7];
    const float* eW1      = (const float*)d_in[8];
    const float* ew2      = (const float*)d_in[9];
    const float* eW3      = (const float*)d_in[10];
    const int* ng_src     = (const int*)d_in[11];
    const int* ng_dst     = (const int*)d_in[12];
    const int* local_src  = (const int*)d_in[13];
    const int* local_dst  = (const int*)d_in[14];
    const int* int_dst    = (const int*)d_in[16];
    const int* sim_dst    = (const int*)d_in[18];

    const int V      = in_sizes[0] / D;
    const int E_NG   = in_sizes[11];
    const int E_LOC  = in_sizes[13];
    const int E_INT  = in_sizes[15];
    const int E_SIM  = in_sizes[17];
    const int E_ALL  = E_NG + E_LOC + E_INT + E_SIM;

    float* out = (float*)d_out;

    int* pCnt;
    cudaGetSymbolAddress((void**)&pCnt, g_cnt);

    cudaMemsetAsync(pCnt, 0, 4 * V_MAX * sizeof(int));

    // phase1: fused count + scores
    int CB = (E_ALL + 255) / 256;
    int SB = (V + 31) / 32;
    phase1_kernel<<<CB + SB, 256>>>(ng_dst, E_NG, local_dst, E_LOC,
                                    int_dst, E_INT, sim_dst, E_SIM, CB,
                                    local_N, global_N, lW1, lw2, gW1, gw2, V, SB);

    // scans
    dim3 sgrid(NBMAX, 4);
    scan1_kernel<<<sgrid, 256>>>(V);
    scan2_kernel<<<4, 128>>>(V);
    scan3_kernel<<<sgrid, 256>>>(V);

    // scatter
    scatter_kernel<<<(E_ALL + 255) / 256, 256>>>(ng_dst, ng_src, E_NG,
                                                 local_dst, local_src, E_LOC,
                                                 int_dst, E_INT, sim_dst, E_SIM);

    // fused per-node-pair gathers + attention + output
    int pairs = (V + 1) / 2;
    node_kernel<<<(pairs * 32 + 255) / 256, 256>>>(out, edge_E, E_INT, Ws, eW1, ew2, eW3, V);
}